// round 15
// baseline (speedup 1.0000x reference)
#include <cuda_runtime.h>
#include <math.h>

#define N_STATES 2048
#define NMASK    2047
#define V_TOK    10000
#define B_       4
#define T_       16
#define L_       16

#define NTHR       1024
#define EMIS_CTAS  512                  // 4 rows per CTA
#define GRID_      (B_ + EMIS_CTAS)     // 4 forward + 512 emis

// scratch: emis[b][t][n] = sum_l E_ls[n, tok[b,t,l]]
__device__ float    g_emis[B_ * T_ * N_STATES];
__device__ unsigned g_count = 0;   // emis CTAs done (reset to 0 each launch)
__device__ unsigned g_fwd   = 0;   // forward CTAs past spin (reset each launch)

// order-preserving float <-> uint key
__device__ __forceinline__ unsigned f2key(float f) {
    unsigned u = __float_as_uint(f);
    return u ^ (((int)u >> 31) | 0x80000000u);
}
__device__ __forceinline__ float key2f(unsigned k) {
    return __uint_as_float(k ^ ((~((int)k >> 31)) | 0x80000000u));
}

// ---------------------------------------------------------------------------
// Fused kernel. Blocks 0..3: forward recurrence (R11 body, b = blockIdx.x),
// prologue overlaps emis, then spins on g_count. Blocks 4..515: emission
// row-logsumexp, 4 rows/CTA (one per 256-thread group), then signal.
// ---------------------------------------------------------------------------
__global__ void __launch_bounds__(NTHR, 1) fused_kernel(
    const float* __restrict__ Ew,
    const int*   __restrict__ stories,
    const float* __restrict__ trans_w,
    const float* __restrict__ prior_w,
    float*       __restrict__ out)
{
    // ---- forward shared ----
    __shared__ float    pbuf[2][N_STATES];
    __shared__ unsigned s_am[3];
    __shared__ float    s_EMadj[T_];
    __shared__ float    s_emp[32];
    __shared__ float    s_red[32];
    __shared__ float    s_plse;
    // ---- emis shared ----
    __shared__ int      e_tok[B_ * T_ * L_];   // 1024
    __shared__ float    e_s[4][8];
    __shared__ float    e_M[4];
    __shared__ float    e_lse[4];
    __shared__ int      e_need[4];

    const int tid  = threadIdx.x;
    const int wid  = tid >> 5;
    const int lane = tid & 31;

    if (blockIdx.x >= B_) {
        // ================= EMIS PART (4 rows per CTA) =====================
        const int g   = tid >> 8;        // group 0..3
        const int gt  = tid & 255;
        const int row = (blockIdx.x - B_) * 4 + g;
        const float*  __restrict__ rowp = Ew + (size_t)row * V_TOK;
        const float4* __restrict__ row4 = (const float4*)rowp;  // 16B aligned

        e_tok[tid] = stories[tid];

        const float C1 = 1.44269504f;    // log2(e)
        const float C0 = -11.5415603f;   // -8*log2(e)
        float s = 0.f;
        #pragma unroll
        for (int j = 0; j < (V_TOK / 4 + 255) / 256; j++) {
            const int i = gt + j * 256;
            if (i < V_TOK / 4) {
                float4 v = row4[i];
                s += exp2f(fmaf(v.x, C1, C0)) + exp2f(fmaf(v.y, C1, C0))
                   + exp2f(fmaf(v.z, C1, C0)) + exp2f(fmaf(v.w, C1, C0));
            }
        }
        #pragma unroll
        for (int o = 16; o > 0; o >>= 1) s += __shfl_xor_sync(0xFFFFFFFFu, s, o);
        if ((gt & 31) == 0) e_s[g][gt >> 5] = s;
        __syncthreads();
        if (gt == 0) {
            float S = e_s[g][0];
            #pragma unroll
            for (int j = 1; j < 8; j++) S += e_s[g][j];
            if (S > 1e-30f && S < 1e30f) { e_need[g] = 0; e_lse[g] = 8.f + __logf(S); }
            else                         { e_need[g] = 1; }
        }
        __syncthreads();

        // uniform fallback: ALL groups enter if ANY group needs it
        const int any = e_need[0] | e_need[1] | e_need[2] | e_need[3];
        if (any) {   // block-uniform branch; rare exact path
            float m = -INFINITY;
            for (int i = gt; i < V_TOK / 4; i += 256) {
                float4 v = row4[i];
                m = fmaxf(m, fmaxf(fmaxf(v.x, v.y), fmaxf(v.z, v.w)));
            }
            #pragma unroll
            for (int o = 16; o > 0; o >>= 1) m = fmaxf(m, __shfl_xor_sync(0xFFFFFFFFu, m, o));
            if ((gt & 31) == 0) e_s[g][gt >> 5] = m;
            __syncthreads();
            if (gt == 0) {
                float M = e_s[g][0];
                #pragma unroll
                for (int j = 1; j < 8; j++) M = fmaxf(M, e_s[g][j]);
                e_M[g] = M;
            }
            __syncthreads();
            const float M = e_M[g];
            float s2 = 0.f;
            for (int i = gt; i < V_TOK / 4; i += 256) {
                float4 v = row4[i];
                s2 += __expf(v.x - M) + __expf(v.y - M)
                    + __expf(v.z - M) + __expf(v.w - M);
            }
            #pragma unroll
            for (int o = 16; o > 0; o >>= 1) s2 += __shfl_xor_sync(0xFFFFFFFFu, s2, o);
            if ((gt & 31) == 0) e_s[g][gt >> 5] = s2;
            __syncthreads();
            if (gt == 0 && e_need[g]) {
                float S = e_s[g][0];
                #pragma unroll
                for (int j = 1; j < 8; j++) S += e_s[g][j];
                e_lse[g] = M + __logf(S);
            }
            __syncthreads();
        }
        const float lse = e_lse[g];

        // gather: 64 (b,t) pairs x 16 tokens for this row (row is cache-hot)
        if (gt < B_ * T_) {
            const int* tk = e_tok + gt * L_;
            float gs = 0.f;
            #pragma unroll
            for (int l = 0; l < L_; l++) gs += __ldg(rowp + tk[l]);
            g_emis[gt * N_STATES + row] = gs - (float)L_ * lse;
        }

        // signal: all 4 rows of this CTA are in g_emis
        __syncthreads();
        __threadfence();
        if (tid == 0) atomicAdd(&g_count, 1u);
        return;
    }

    // ==================== FORWARD PART (blocks 0..3) ======================
    const int b = blockIdx.x;
    const float* __restrict__ emisb = g_emis + (size_t)b * T_ * N_STATES;

    const int h0   = 2 * tid;
    const int im1  = (h0 - 1)    & NMASK;
    const int ip2  = (h0 + 2)    & NMASK;
    const int im32 = (h0 - 32)   & NMASK;
    const int ip32 = (h0 + 32)   & NMASK;
    const int ipk  = (h0 + 1024) & NMASK;   // -1024 == +1024 mod 2048

    if (tid < 3) s_am[tid] = 0u;

    // ---- emis-independent prologue (overlaps emis CTAs) ----
    float Tt[2][6];
    {
        const float2* __restrict__ tw = (const float2*)(trans_w + (size_t)h0 * 7);
        float w[14];
        #pragma unroll
        for (int j = 0; j < 7; j++) {
            const float2 v = __ldg(tw + j);
            w[2 * j] = v.x; w[2 * j + 1] = v.y;
        }
        #pragma unroll
        for (int k = 0; k < 2; k++) {
            float* wk = w + 7 * k;
            float m = wk[0];
            #pragma unroll
            for (int j = 1; j < 7; j++) m = fmaxf(m, wk[j]);
            float e[7], ssum = 0.f;
            #pragma unroll
            for (int j = 0; j < 7; j++) { e[j] = __expf(wk[j] - m); ssum += e[j]; }
            const float inv = 1.0f / ssum;
            Tt[k][0] = e[6] * inv;   // diagonal (slot 6 wins over slot 0)
            Tt[k][1] = e[1] * inv;   // from h-1
            Tt[k][2] = e[2] * inv;   // from h+1
            Tt[k][3] = e[3] * inv;   // from h-32
            Tt[k][4] = e[4] * inv;   // from h+32
            Tt[k][5] = e[5] * inv;   // from h-1024
        }
    }

    const float2 pwv = __ldg((const float2*)(prior_w + h0));

    float pm = fmaxf(pwv.x, pwv.y);
    pm = key2f(__reduce_max_sync(0xFFFFFFFFu, f2key(pm)));
    if (lane == 0) s_red[wid] = pm;
    __syncthreads();

    float PM = s_red[lane];
    PM = key2f(__reduce_max_sync(0xFFFFFFFFu, f2key(PM)));
    __syncthreads();

    float ps = __expf(pwv.x - PM) + __expf(pwv.y - PM);
    #pragma unroll
    for (int o = 16; o > 0; o >>= 1) ps += __shfl_xor_sync(0xFFFFFFFFu, ps, o);
    if (lane == 0) s_red[wid] = ps;
    __syncthreads();
    if (tid == 0) {
        float ss = 0.f;
        #pragma unroll
        for (int j = 0; j < 32; j++) ss += s_red[j];
        s_plse = PM + __logf(ss);
    }
    __syncthreads();
    const float plse = s_plse;

    // ---- wait for all emis CTAs (producer fence + counter) ----
    if (tid == 0) {
        while (atomicAdd(&g_count, 0u) < (unsigned)EMIS_CTAS) __nanosleep(64);
        // counter reset: the 4th forward CTA past the spin zeroes both
        // counters (all 512 increments have landed; nobody reads them again
        // this launch) -> every launch starts AND ends at 0: deterministic.
        const unsigned old = atomicAdd(&g_fwd, 1u);
        if (old == (unsigned)(B_ - 1)) {
            atomicExch(&g_count, 0u);
            atomicExch(&g_fwd, 0u);
        }
    }
    __syncthreads();
    __threadfence();

    // ---- EM[t] = max_n emis[t][n] : 2 warps per timestep, LDG.128 ----
    {
        const int t = wid >> 1, half = wid & 1;
        const float4* eb4 = (const float4*)(emisb + t * N_STATES + half * 1024);
        float mx = -INFINITY;
        #pragma unroll
        for (int j = 0; j < 8; j++) {
            const float4 v = __ldg(eb4 + lane + j * 32);
            mx = fmaxf(mx, fmaxf(fmaxf(v.x, v.y), fmaxf(v.z, v.w)));
        }
        mx = key2f(__reduce_max_sync(0xFFFFFFFFu, f2key(mx)));
        if (lane == 0) s_emp[wid] = mx;
    }
    __syncthreads();

    if (tid < T_)
        s_EMadj[tid] = (tid == 0) ? 0.f
                     : fmaxf(s_emp[2 * tid], s_emp[2 * tid + 1]) + 2.0f;

    // ---- alpha0 (atomics into slot 0 and slot 2) ----
    float a0, a1;
    {
        const float2 e0 = __ldg((const float2*)(emisb + h0));
        a0 = e0.x + pwv.x - plse;
        a1 = e0.y + pwv.y - plse;
        *(float2*)(out + b * N_STATES + h0) = make_float2(a0, a1);
        const unsigned k = __reduce_max_sync(0xFFFFFFFFu, f2key(fmaxf(a0, a1)));
        if (lane == 0) {
            atomicMax(&s_am[0], k);
            atomicMax(&s_am[2], k);
        }
    }
    __syncthreads();   // BAR_0 (covers s_EMadj writes + alpha0 atomics)

    // ---- recurrence: one barrier per step, fully unrolled ----
    const float* __restrict__ ep   = emisb;
    float*       __restrict__ outp = out + b * N_STATES;

    #pragma unroll
    for (int t = 1; t < T_; t++) {
        ep   += N_STATES;
        outp += B_ * N_STATES;
        const int qs = t & 1;
        const int ws = t % 3;           // write slot
        const int rs = (t + 1) % 3;     // read/reset slot: blockmax(a_{t-2})

        // ---- phase A: normalizer + publish q ----
        const float m = key2f(s_am[rs]) + s_EMadj[t - 1];
        const float q0 = __expf(a0 - m);
        const float q1 = __expf(a1 - m);
        *(float2*)&pbuf[qs][h0] = make_float2(q0, q1);
        const float2 em = __ldg((const float2*)(ep + h0));  // prefetch across BAR
        __syncthreads();   // BAR_t

        // ---- phase B: 6-tap weighted sums + log ----
        const float2 vm = *(const float2*)&pbuf[qs][im32];
        const float2 vp = *(const float2*)&pbuf[qs][ip32];
        const float2 vk = *(const float2*)&pbuf[qs][ipk];
        const float  v1 = pbuf[qs][im1];
        const float  v2 = pbuf[qs][ip2];

        float s0 = Tt[0][0] * q0;
        s0 = fmaf(Tt[0][1], v1,   s0);
        s0 = fmaf(Tt[0][2], q1,   s0);
        s0 = fmaf(Tt[0][3], vm.x, s0);
        s0 = fmaf(Tt[0][4], vp.x, s0);
        s0 = fmaf(Tt[0][5], vk.x, s0);
        float s1 = Tt[1][0] * q1;
        s1 = fmaf(Tt[1][1], q0,   s1);
        s1 = fmaf(Tt[1][2], v2,   s1);
        s1 = fmaf(Tt[1][3], vm.y, s1);
        s1 = fmaf(Tt[1][4], vp.y, s1);
        s1 = fmaf(Tt[1][5], vk.y, s1);
        s0 = fmaxf(s0, 1e-37f);
        s1 = fmaxf(s1, 1e-37f);
        a0 = em.x + m + __logf(s0);
        a1 = em.y + m + __logf(s1);
        *(float2*)(outp + h0) = make_float2(a0, a1);

        const unsigned k = __reduce_max_sync(0xFFFFFFFFu, f2key(fmaxf(a0, a1)));
        if (lane == 0) atomicMax(&s_am[ws], k);   // read at A_{t+2}
        if (tid == 0)  s_am[rs] = 0u;             // reset just-read slot
    }
}

// ---------------------------------------------------------------------------
extern "C" void kernel_launch(void* const* d_in, const int* in_sizes, int n_in,
                              void* d_out, int out_size)
{
    const int*   stories = nullptr;
    const float* trans_w = nullptr;
    const float* emis_w  = nullptr;
    const float* prior_w = nullptr;
    for (int i = 0; i < n_in; i++) {
        switch (in_sizes[i]) {
            case B_ * T_ * L_:     stories = (const int*)d_in[i];   break;
            case N_STATES * 7:     trans_w = (const float*)d_in[i]; break;
            case N_STATES * V_TOK: emis_w  = (const float*)d_in[i]; break;
            case N_STATES:         prior_w = (const float*)d_in[i]; break;
            default: break; // story_length scalar unused (compile-time T_)
        }
    }
    float* out = (float*)d_out;

    fused_kernel<<<GRID_, NTHR>>>(emis_w, stories, trans_w, prior_w, out);
}

// round 16
// speedup vs baseline: 1.2857x; 1.2857x over previous
#include <cuda_runtime.h>
#include <math.h>

#define N_STATES 2048
#define NMASK    2047
#define V_TOK    10000
#define B_       4
#define T_       16
#define L_       16

#define FTPB 1024

// scratch: emis[b][t][n] = sum_l E_ls[n, tok[b,t,l]]
__device__ float g_emis[B_ * T_ * N_STATES];

// order-preserving float <-> uint key
__device__ __forceinline__ unsigned f2key(float f) {
    unsigned u = __float_as_uint(f);
    return u ^ (((int)u >> 31) | 0x80000000u);
}
__device__ __forceinline__ float key2f(unsigned k) {
    return __uint_as_float(k ^ ((~((int)k >> 31)) | 0x80000000u));
}

// ---------------------------------------------------------------------------
// Kernel 1: fixed-shift (no-max) logsumexp per state row; exact two-pass
// fallback only if the shifted sum leaves fp32 range. Gather threads read
// their 16 tokens directly from global (L2-hot, coalesced int4) — no smem
// staging of the stories array (saves 8MB of L2 traffic across the grid).
// ---------------------------------------------------------------------------
__global__ void __launch_bounds__(256) emis_kernel(const float* __restrict__ Ew,
                                                   const int* __restrict__ stories)
{
    const int n   = blockIdx.x;
    const int tid = threadIdx.x;
    const float* __restrict__ row  = Ew + (size_t)n * V_TOK;
    const float4* __restrict__ row4 = (const float4*)row;   // n*40000B, 16B aligned

    __shared__ float s_s[8];
    __shared__ float s_lse;
    __shared__ int   s_need2;

    const float C1 = 1.44269504f;       // log2(e)
    const float C0 = -11.5415603f;      // -8 * log2(e)
    float s = 0.f;
    #pragma unroll
    for (int j = 0; j < (V_TOK / 4 + 255) / 256; j++) {
        const int i = tid + j * 256;
        if (i < V_TOK / 4) {
            float4 v = row4[i];
            s += exp2f(fmaf(v.x, C1, C0)) + exp2f(fmaf(v.y, C1, C0))
               + exp2f(fmaf(v.z, C1, C0)) + exp2f(fmaf(v.w, C1, C0));
        }
    }
    #pragma unroll
    for (int o = 16; o > 0; o >>= 1) s += __shfl_xor_sync(0xFFFFFFFFu, s, o);
    if ((tid & 31) == 0) s_s[tid >> 5] = s;
    __syncthreads();
    if (tid == 0) {
        float S = s_s[0];
        #pragma unroll
        for (int j = 1; j < 8; j++) S += s_s[j];
        if (S > 1e-30f && S < 1e30f) { s_need2 = 0; s_lse = 8.f + __logf(S); }
        else                         { s_need2 = 1; }
    }
    __syncthreads();

    if (s_need2) {  // rare exact path (row is L1/L2-hot)
        float m = -INFINITY;
        for (int i = tid; i < V_TOK / 4; i += 256) {
            float4 v = row4[i];
            m = fmaxf(m, fmaxf(fmaxf(v.x, v.y), fmaxf(v.z, v.w)));
        }
        #pragma unroll
        for (int o = 16; o > 0; o >>= 1) m = fmaxf(m, __shfl_xor_sync(0xFFFFFFFFu, m, o));
        if ((tid & 31) == 0) s_s[tid >> 5] = m;
        __syncthreads();
        float M = s_s[0];
        #pragma unroll
        for (int j = 1; j < 8; j++) M = fmaxf(M, s_s[j]);
        __syncthreads();

        float s2 = 0.f;
        for (int i = tid; i < V_TOK / 4; i += 256) {
            float4 v = row4[i];
            s2 += __expf(v.x - M) + __expf(v.y - M)
                + __expf(v.z - M) + __expf(v.w - M);
        }
        #pragma unroll
        for (int o = 16; o > 0; o >>= 1) s2 += __shfl_xor_sync(0xFFFFFFFFu, s2, o);
        if ((tid & 31) == 0) s_s[tid >> 5] = s2;
        __syncthreads();
        if (tid == 0) {
            float S = 0.f;
            #pragma unroll
            for (int j = 0; j < 8; j++) S += s_s[j];
            s_lse = M + __logf(S);
        }
        __syncthreads();
    }
    const float lse = s_lse;

    // gather: 64 (b,t) pairs x 16 tokens; tokens straight from global
    // (contiguous 64B per thread, int4 x4, L2-hot); row is L1-hot.
    if (tid < B_ * T_) {
        const int4* __restrict__ tk4 = (const int4*)(stories + tid * L_);
        float g = 0.f;
        #pragma unroll
        for (int q = 0; q < 4; q++) {
            const int4 tk = __ldg(tk4 + q);
            g += __ldg(row + tk.x) + __ldg(row + tk.y)
               + __ldg(row + tk.z) + __ldg(row + tk.w);
        }
        g_emis[tid * N_STATES + n] = g - (float)L_ * lse;
    }
}

// ---------------------------------------------------------------------------
// Kernel 2: forward recurrence (R6/R11 structure — best verified, byte-
// identical to R11). Contiguous state pair per thread; lagged normalizer
// m_t = blockmax(a_{t-2}) + EM[t-1] + 2 via 3-slot atomicMax key ring; warp
// max via REDUX. One barrier per step; fully unrolled.
// Transition band: delta=2048 aliases delta=0 (mod N); scatter-set order
// means slot 6 wins the diagonal, slot 0 is dead.
// ---------------------------------------------------------------------------
__global__ void __launch_bounds__(FTPB) forward_kernel(
    const float* __restrict__ trans_w,
    const float* __restrict__ prior_w,
    float* __restrict__ out)
{
    __shared__ float    pbuf[2][N_STATES];
    __shared__ unsigned s_am[3];          // blockmax key ring
    __shared__ float    s_EMadj[T_];      // [0]=0, [t]=EM[t]+2
    __shared__ float    s_emp[32];
    __shared__ float    s_red[32];
    __shared__ float    s_plse;

    const int b    = blockIdx.x;
    const int tid  = threadIdx.x;
    const int wid  = tid >> 5;
    const int lane = tid & 31;

    const float* __restrict__ emisb = g_emis + (size_t)b * T_ * N_STATES;

    const int h0   = 2 * tid;
    const int im1  = (h0 - 1)    & NMASK;
    const int ip2  = (h0 + 2)    & NMASK;
    const int im32 = (h0 - 32)   & NMASK;
    const int ip32 = (h0 + 32)   & NMASK;
    const int ipk  = (h0 + 1024) & NMASK;   // -1024 == +1024 mod 2048

    if (tid < 3) s_am[tid] = 0u;

    // ---- per-thread transition softmax for states h0, h0+1 (registers) ----
    float Tt[2][6];
    {
        const float2* __restrict__ tw = (const float2*)(trans_w + (size_t)h0 * 7);
        float w[14];
        #pragma unroll
        for (int j = 0; j < 7; j++) {
            const float2 v = __ldg(tw + j);
            w[2 * j] = v.x; w[2 * j + 1] = v.y;
        }
        #pragma unroll
        for (int k = 0; k < 2; k++) {
            float* wk = w + 7 * k;
            float m = wk[0];
            #pragma unroll
            for (int j = 1; j < 7; j++) m = fmaxf(m, wk[j]);
            float e[7], ssum = 0.f;
            #pragma unroll
            for (int j = 0; j < 7; j++) { e[j] = __expf(wk[j] - m); ssum += e[j]; }
            const float inv = 1.0f / ssum;
            Tt[k][0] = e[6] * inv;   // diagonal (slot 6 wins over slot 0)
            Tt[k][1] = e[1] * inv;   // from h-1
            Tt[k][2] = e[2] * inv;   // from h+1
            Tt[k][3] = e[3] * inv;   // from h-32
            Tt[k][4] = e[4] * inv;   // from h+32
            Tt[k][5] = e[5] * inv;   // from h-1024
        }
    }

    // ---- EM[t] = max_n emis[t][n] : 2 warps per timestep, LDG.128 ----
    {
        const int t = wid >> 1, half = wid & 1;
        const float4* eb4 = (const float4*)(emisb + t * N_STATES + half * 1024);
        float mx = -INFINITY;
        #pragma unroll
        for (int j = 0; j < 8; j++) {
            const float4 v = __ldg(eb4 + lane + j * 32);
            mx = fmaxf(mx, fmaxf(fmaxf(v.x, v.y), fmaxf(v.z, v.w)));
        }
        mx = key2f(__reduce_max_sync(0xFFFFFFFFu, f2key(mx)));
        if (lane == 0) s_emp[wid] = mx;
    }

    // ---- prior logsumexp ----
    const float2 pwv = __ldg((const float2*)(prior_w + h0));

    float pm = fmaxf(pwv.x, pwv.y);
    pm = key2f(__reduce_max_sync(0xFFFFFFFFu, f2key(pm)));
    if (lane == 0) s_red[wid] = pm;
    __syncthreads();

    if (tid < T_)
        s_EMadj[tid] = (tid == 0) ? 0.f
                     : fmaxf(s_emp[2 * tid], s_emp[2 * tid + 1]) + 2.0f;

    float PM = s_red[lane];
    PM = key2f(__reduce_max_sync(0xFFFFFFFFu, f2key(PM)));
    __syncthreads();

    float ps = __expf(pwv.x - PM) + __expf(pwv.y - PM);
    #pragma unroll
    for (int o = 16; o > 0; o >>= 1) ps += __shfl_xor_sync(0xFFFFFFFFu, ps, o);
    if (lane == 0) s_red[wid] = ps;
    __syncthreads();
    if (tid == 0) {
        float ss = 0.f;
        #pragma unroll
        for (int j = 0; j < 32; j++) ss += s_red[j];
        s_plse = PM + __logf(ss);
    }
    __syncthreads();
    const float plse = s_plse;

    // ---- alpha0 (atomics into slot 0 and slot 2) ----
    float a0, a1;
    {
        const float2 e0 = __ldg((const float2*)(emisb + h0));
        a0 = e0.x + pwv.x - plse;
        a1 = e0.y + pwv.y - plse;
        *(float2*)(out + b * N_STATES + h0) = make_float2(a0, a1);
        const unsigned k = __reduce_max_sync(0xFFFFFFFFu, f2key(fmaxf(a0, a1)));
        if (lane == 0) {
            atomicMax(&s_am[0], k);
            atomicMax(&s_am[2], k);
        }
    }
    __syncthreads();   // BAR_0

    // ---- recurrence: one barrier per step, fully unrolled ----
    const float* __restrict__ ep   = emisb;
    float*       __restrict__ outp = out + b * N_STATES;

    #pragma unroll
    for (int t = 1; t < T_; t++) {
        ep   += N_STATES;
        outp += B_ * N_STATES;
        const int qs = t & 1;
        const int ws = t % 3;           // write slot
        const int rs = (t + 1) % 3;     // read/reset slot: blockmax(a_{t-2})

        // ---- phase A: normalizer + publish q ----
        const float m = key2f(s_am[rs]) + s_EMadj[t - 1];
        const float q0 = __expf(a0 - m);
        const float q1 = __expf(a1 - m);
        *(float2*)&pbuf[qs][h0] = make_float2(q0, q1);
        const float2 em = __ldg((const float2*)(ep + h0));  // prefetch across BAR
        __syncthreads();   // BAR_t

        // ---- phase B: 6-tap weighted sums + log ----
        const float2 vm = *(const float2*)&pbuf[qs][im32];
        const float2 vp = *(const float2*)&pbuf[qs][ip32];
        const float2 vk = *(const float2*)&pbuf[qs][ipk];
        const float  v1 = pbuf[qs][im1];
        const float  v2 = pbuf[qs][ip2];

        float s0 = Tt[0][0] * q0;
        s0 = fmaf(Tt[0][1], v1,   s0);
        s0 = fmaf(Tt[0][2], q1,   s0);
        s0 = fmaf(Tt[0][3], vm.x, s0);
        s0 = fmaf(Tt[0][4], vp.x, s0);
        s0 = fmaf(Tt[0][5], vk.x, s0);
        float s1 = Tt[1][0] * q1;
        s1 = fmaf(Tt[1][1], q0,   s1);
        s1 = fmaf(Tt[1][2], v2,   s1);
        s1 = fmaf(Tt[1][3], vm.y, s1);
        s1 = fmaf(Tt[1][4], vp.y, s1);
        s1 = fmaf(Tt[1][5], vk.y, s1);
        s0 = fmaxf(s0, 1e-37f);
        s1 = fmaxf(s1, 1e-37f);
        a0 = em.x + m + __logf(s0);
        a1 = em.y + m + __logf(s1);
        *(float2*)(outp + h0) = make_float2(a0, a1);

        const unsigned k = __reduce_max_sync(0xFFFFFFFFu, f2key(fmaxf(a0, a1)));
        if (lane == 0) atomicMax(&s_am[ws], k);   // read at A_{t+2}
        if (tid == 0)  s_am[rs] = 0u;             // reset just-read slot
    }
}

// ---------------------------------------------------------------------------
extern "C" void kernel_launch(void* const* d_in, const int* in_sizes, int n_in,
                              void* d_out, int out_size)
{
    const int*   stories = nullptr;
    const float* trans_w = nullptr;
    const float* emis_w  = nullptr;
    const float* prior_w = nullptr;
    for (int i = 0; i < n_in; i++) {
        switch (in_sizes[i]) {
            case B_ * T_ * L_:     stories = (const int*)d_in[i];   break;
            case N_STATES * 7:     trans_w = (const float*)d_in[i]; break;
            case N_STATES * V_TOK: emis_w  = (const float*)d_in[i]; break;
            case N_STATES:         prior_w = (const float*)d_in[i]; break;
            default: break; // story_length scalar unused (compile-time T_)
        }
    }
    float* out = (float*)d_out;

    emis_kernel<<<N_STATES, 256>>>(emis_w, stories);
    forward_kernel<<<B_, FTPB>>>(trans_w, prior_w, out);
}